// round 2
// baseline (speedup 1.0000x reference)
#include <cuda_runtime.h>
#include <math.h>

// Problem constants
#define Bsz 2
#define Ssz 2048
#define Dsz 1024
#define Hsz 16
#define DKsz 64
#define BHsz (Bsz * Hsz)

// Scratch (allocation-free rule: __device__ globals)
__device__ float g_Q[(long)Bsz * Ssz * Dsz];
__device__ float g_K[(long)Bsz * Ssz * Dsz];
__device__ float g_V[(long)Bsz * Ssz * Dsz];
__device__ float g_X[(long)Bsz * Ssz * Dsz];

// ---------------------------------------------------------------------------
// Generic 64x64 tile GEMM core: C = scale * (A @ B)   (or A @ B^T if TRANSB)
// A: [M,K] row-major with leading dim lda
// B (NN): [K,N] row-major ldb; B (NT): [N,K] row-major ldb
// 256 threads, each computes a 4x4 microtile. K must be a multiple of 16.
// All dims used here are multiples of 64 so no bounds checks.
// ---------------------------------------------------------------------------
template <bool TRANSB>
__device__ __forceinline__ void gemm_tile(const float* __restrict__ A, int lda,
                                          const float* __restrict__ B, int ldb,
                                          float* __restrict__ C, int ldc,
                                          int K, float scale) {
    __shared__ __align__(16) float As[16][68];
    __shared__ __align__(16) float Bs[16][68];

    const int t  = threadIdx.x;       // 0..255
    const int tx = t & 15;            // 0..15
    const int ty = t >> 4;            // 0..15
    const int row0 = blockIdx.y * 64;
    const int col0 = blockIdx.x * 64;

    // Per-thread float4 load coords (64 rows x 16 cols tile)
    const int ldRow  = t >> 2;        // 0..63
    const int ldCol4 = (t & 3) * 4;   // 0,4,8,12
    // NN B tile load coords (16 k-rows x 64 n-cols)
    const int bK  = t >> 4;           // 0..15
    const int bN4 = (t & 15) * 4;     // 0..60

    float acc[4][4];
#pragma unroll
    for (int i = 0; i < 4; i++)
#pragma unroll
        for (int j = 0; j < 4; j++) acc[i][j] = 0.0f;

    for (int k0 = 0; k0 < K; k0 += 16) {
        // Load A tile [64 x 16], store transposed As[k][m]
        {
            float4 av = *reinterpret_cast<const float4*>(
                A + (long)(row0 + ldRow) * lda + k0 + ldCol4);
            As[ldCol4 + 0][ldRow] = av.x;
            As[ldCol4 + 1][ldRow] = av.y;
            As[ldCol4 + 2][ldRow] = av.z;
            As[ldCol4 + 3][ldRow] = av.w;
        }
        if (TRANSB) {
            // B logical [K,N] but stored as [N,K]: load rows of Bmat (n), cols k
            float4 bv = *reinterpret_cast<const float4*>(
                B + (long)(col0 + ldRow) * ldb + k0 + ldCol4);
            Bs[ldCol4 + 0][ldRow] = bv.x;
            Bs[ldCol4 + 1][ldRow] = bv.y;
            Bs[ldCol4 + 2][ldRow] = bv.z;
            Bs[ldCol4 + 3][ldRow] = bv.w;
        } else {
            float4 bv = *reinterpret_cast<const float4*>(
                B + (long)(k0 + bK) * ldb + col0 + bN4);
            *reinterpret_cast<float4*>(&Bs[bK][bN4]) = bv;
        }
        __syncthreads();

#pragma unroll
        for (int k = 0; k < 16; k++) {
            float4 a4 = *reinterpret_cast<const float4*>(&As[k][ty * 4]);
            float4 b4 = *reinterpret_cast<const float4*>(&Bs[k][tx * 4]);
            float a[4] = {a4.x, a4.y, a4.z, a4.w};
            float b[4] = {b4.x, b4.y, b4.z, b4.w};
#pragma unroll
            for (int i = 0; i < 4; i++)
#pragma unroll
                for (int j = 0; j < 4; j++) acc[i][j] = fmaf(a[i], b[j], acc[i][j]);
        }
        __syncthreads();
    }

#pragma unroll
    for (int i = 0; i < 4; i++) {
        float4 out;
        out.x = acc[i][0] * scale;
        out.y = acc[i][1] * scale;
        out.z = acc[i][2] * scale;
        out.w = acc[i][3] * scale;
        *reinterpret_cast<float4*>(
            C + (long)(row0 + ty * 4 + i) * ldc + col0 + tx * 4) = out;
    }
}

// ---------------------------------------------------------------------------
// Kernel wrappers
// ---------------------------------------------------------------------------

// Y[M,N] = X[M,K] @ W[K,N]; M=4096, N=K=1024. grid (16, 64)
__global__ void proj_kernel(const float* __restrict__ X,
                            const float* __restrict__ W,
                            float* __restrict__ Y) {
    gemm_tile<false>(X, Dsz, W, Dsz, Y, Dsz, Dsz, 1.0f);
}

// scores[z, q, k] = (1/8) * Q[z,q,:] . K[z,k,:]; grid (32, 32, 32)
__global__ void scores_kernel(float* __restrict__ attn) {
    const int z = blockIdx.z;
    const int b = z / Hsz, h = z % Hsz;
    const float* A  = g_Q + (long)b * Ssz * Dsz + h * DKsz;
    const float* Bm = g_K + (long)b * Ssz * Dsz + h * DKsz;
    float* C = attn + (long)z * Ssz * Ssz;
    gemm_tile<true>(A, Dsz, Bm, Dsz, C, Ssz, DKsz, 0.125f);
}

// Row softmax in place with mask. grid (Ssz, BHsz), block 256
__global__ void softmax_kernel(float* __restrict__ attn,
                               const int* __restrict__ mask) {
    const int row = blockIdx.x;
    const int z   = blockIdx.y;
    const int b   = z / Hsz;
    float* rp = attn + ((long)z * Ssz + row) * Ssz;
    const int* mp = mask + ((long)b * Ssz + row) * Ssz;
    const int t = threadIdx.x;

    float vals[8];
    float mx = -1e30f;
#pragma unroll
    for (int i = 0; i < 8; i++) {
        const int k = t + i * 256;
        float v = rp[k];
        if (mp[k] == 0) v = -1e9f;
        vals[i] = v;
        mx = fmaxf(mx, v);
    }

    __shared__ float red[256];
    red[t] = mx;
    __syncthreads();
#pragma unroll
    for (int s = 128; s > 0; s >>= 1) {
        if (t < s) red[t] = fmaxf(red[t], red[t + s]);
        __syncthreads();
    }
    mx = red[0];
    __syncthreads();

    float sum = 0.0f;
#pragma unroll
    for (int i = 0; i < 8; i++) {
        vals[i] = __expf(vals[i] - mx);
        sum += vals[i];
    }
    red[t] = sum;
    __syncthreads();
#pragma unroll
    for (int s = 128; s > 0; s >>= 1) {
        if (t < s) red[t] += red[t + s];
        __syncthreads();
    }
    const float inv = 1.0f / red[0];

#pragma unroll
    for (int i = 0; i < 8; i++) {
        const int k = t + i * 256;
        rp[k] = vals[i] * inv;
    }
}

// X[z, q, :] = attn[z] @ V[z]; M=2048, N=64, K=2048. grid (1, 32, 32)
__global__ void av_kernel(const float* __restrict__ attn) {
    const int z = blockIdx.z;
    const int b = z / Hsz, h = z % Hsz;
    const float* A  = attn + (long)z * Ssz * Ssz;
    const float* Bm = g_V + (long)b * Ssz * Dsz + h * DKsz;
    float* C = g_X + (long)b * Ssz * Dsz + h * DKsz;
    gemm_tile<false>(A, Ssz, Bm, Dsz, C, Dsz, Ssz, 1.0f);
}

// ---------------------------------------------------------------------------
// Launch
// ---------------------------------------------------------------------------
extern "C" void kernel_launch(void* const* d_in, const int* in_sizes, int n_in,
                              void* d_out, int out_size) {
    const float* query = (const float*)d_in[0];
    const float* key   = (const float*)d_in[1];
    const float* value = (const float*)d_in[2];
    const int*   mask  = (const int*)d_in[3];
    const float* W_q   = (const float*)d_in[4];
    const float* W_k   = (const float*)d_in[5];
    const float* W_v   = (const float*)d_in[6];
    const float* W_o   = (const float*)d_in[7];

    float* out  = (float*)d_out;                        // (B,S,D)
    float* attn = out + (long)Bsz * Ssz * Dsz;          // (B,H,S,S)

    float *Q, *K, *V, *X;
    cudaGetSymbolAddress((void**)&Q, g_Q);
    cudaGetSymbolAddress((void**)&K, g_K);
    cudaGetSymbolAddress((void**)&V, g_V);
    cudaGetSymbolAddress((void**)&X, g_X);

    dim3 projGrid(Dsz / 64, (Bsz * Ssz) / 64);          // (16, 64)
    proj_kernel<<<projGrid, 256>>>(query, W_q, Q);
    proj_kernel<<<projGrid, 256>>>(key,   W_k, K);
    proj_kernel<<<projGrid, 256>>>(value, W_v, V);

    scores_kernel<<<dim3(Ssz / 64, Ssz / 64, BHsz), 256>>>(attn);
    softmax_kernel<<<dim3(Ssz, BHsz), 256>>>(attn, mask);
    av_kernel<<<dim3(1, Ssz / 64, BHsz), 256>>>(attn);

    proj_kernel<<<projGrid, 256>>>(X, W_o, out);
}

// round 6
// speedup vs baseline: 2.8069x; 2.8069x over previous
#include <cuda_runtime.h>
#include <math.h>

// Problem constants
#define Bsz 2
#define Ssz 2048
#define Dsz 1024
#define Hsz 16
#define DKsz 64
#define BHsz (Bsz * Hsz)

// Scratch (allocation-free rule: __device__ globals)
__device__ float g_Q[(long)Bsz * Ssz * Dsz];
__device__ float g_K[(long)Bsz * Ssz * Dsz];
__device__ float g_V[(long)Bsz * Ssz * Dsz];
__device__ float g_X[(long)Bsz * Ssz * Dsz];

__device__ __forceinline__ unsigned f2tf(float f) {
    unsigned u;
    asm("cvt.rna.tf32.f32 %0, %1;" : "=r"(u) : "f"(f));
    return u;
}

__device__ __forceinline__ void mma_tf32(float c[4], unsigned a0, unsigned a1,
                                         unsigned a2, unsigned a3,
                                         unsigned b0, unsigned b1) {
    asm volatile(
        "mma.sync.aligned.m16n8k8.row.col.f32.tf32.tf32.f32 "
        "{%0,%1,%2,%3}, {%4,%5,%6,%7}, {%8,%9}, {%0,%1,%2,%3};"
        : "+f"(c[0]), "+f"(c[1]), "+f"(c[2]), "+f"(c[3])
        : "r"(a0), "r"(a1), "r"(a2), "r"(a3), "r"(b0), "r"(b1));
}

// ---------------------------------------------------------------------------
// tf32 tensor-core GEMM: C = scale * (A @ B)  (A @ B^T if TRANSB)
// Block tile 128x64, BK=32, 256 threads (8 warps, each 32x32 warp tile).
// A: [M,K] row-major, lda. B (NN): [K,N] row-major ldb; (NT): [N,K] ldb.
// M % 128 == 0, N % 64 == 0, K % 32 == 0 (true for all shapes here).
// ---------------------------------------------------------------------------
template <bool TRANSB>
__device__ __forceinline__ void gemm_mma(const float* __restrict__ A, int lda,
                                         const float* __restrict__ B, int ldb,
                                         float* __restrict__ C, int ldc,
                                         int K, float scale) {
    __shared__ __align__(16) unsigned As[128][36];            // frag banks (4g+tg)
    __shared__ __align__(16) unsigned Bs[TRANSB ? 64 : 32]
                                        [TRANSB ? 36 : 72];   // NT: (4g+tg), NN: (8tg+g)

    const int t    = threadIdx.x;
    const int lane = t & 31;
    const int warp = t >> 5;
    const int wm   = (warp & 3) * 32;   // warp row offset
    const int wn   = (warp >> 2) * 32;  // warp col offset
    const int g    = lane >> 2;         // 0..7
    const int tg   = lane & 3;          // 0..3

    const int row0 = blockIdx.y * 128;
    const int col0 = blockIdx.x * 64;

    float c[2][4][4];
#pragma unroll
    for (int mi = 0; mi < 2; mi++)
#pragma unroll
        for (int ni = 0; ni < 4; ni++)
#pragma unroll
            for (int r = 0; r < 4; r++) c[mi][ni][r] = 0.0f;

    for (int k0 = 0; k0 < K; k0 += 32) {
        // Stage A tile 128x32 (tf32-converted), 4 float4 per thread
#pragma unroll
        for (int i = 0; i < 4; i++) {
            const int fidx = t + i * 256;
            const int r  = fidx >> 3;
            const int c4 = (fidx & 7) << 2;
            float4 v = *reinterpret_cast<const float4*>(
                A + (long)(row0 + r) * lda + k0 + c4);
            uint4 u = {f2tf(v.x), f2tf(v.y), f2tf(v.z), f2tf(v.w)};
            *reinterpret_cast<uint4*>(&As[r][c4]) = u;
        }
        // Stage B tile, 2 float4 per thread
        if (TRANSB) {
            // B is [N,K]; Bs[n][k]
#pragma unroll
            for (int i = 0; i < 2; i++) {
                const int fidx = t + i * 256;
                const int r  = fidx >> 3;        // n in 0..63
                const int c4 = (fidx & 7) << 2;  // k
                float4 v = *reinterpret_cast<const float4*>(
                    B + (long)(col0 + r) * ldb + k0 + c4);
                uint4 u = {f2tf(v.x), f2tf(v.y), f2tf(v.z), f2tf(v.w)};
                *reinterpret_cast<uint4*>(&Bs[r][c4]) = u;
            }
        } else {
            // B is [K,N]; Bs[k][n]
#pragma unroll
            for (int i = 0; i < 2; i++) {
                const int fidx = t + i * 256;
                const int r  = fidx >> 4;        // k in 0..31
                const int c4 = (fidx & 15) << 2; // n
                float4 v = *reinterpret_cast<const float4*>(
                    B + (long)(k0 + r) * ldb + col0 + c4);
                uint4 u = {f2tf(v.x), f2tf(v.y), f2tf(v.z), f2tf(v.w)};
                *reinterpret_cast<uint4*>(&Bs[r][c4]) = u;
            }
        }
        __syncthreads();

#pragma unroll
        for (int ks = 0; ks < 4; ks++) {
            const int k8 = ks * 8;
            unsigned a[2][4];
#pragma unroll
            for (int mi = 0; mi < 2; mi++) {
                const int mb = wm + mi * 16;
                a[mi][0] = As[mb + g][k8 + tg];
                a[mi][1] = As[mb + g + 8][k8 + tg];
                a[mi][2] = As[mb + g][k8 + tg + 4];
                a[mi][3] = As[mb + g + 8][k8 + tg + 4];
            }
            unsigned b[4][2];
#pragma unroll
            for (int ni = 0; ni < 4; ni++) {
                const int nb = wn + ni * 8;
                if (TRANSB) {
                    b[ni][0] = Bs[nb + g][k8 + tg];
                    b[ni][1] = Bs[nb + g][k8 + tg + 4];
                } else {
                    b[ni][0] = Bs[k8 + tg][nb + g];
                    b[ni][1] = Bs[k8 + tg + 4][nb + g];
                }
            }
#pragma unroll
            for (int mi = 0; mi < 2; mi++)
#pragma unroll
                for (int ni = 0; ni < 4; ni++)
                    mma_tf32(c[mi][ni], a[mi][0], a[mi][1], a[mi][2], a[mi][3],
                             b[ni][0], b[ni][1]);
        }
        __syncthreads();
    }

    // Epilogue
#pragma unroll
    for (int mi = 0; mi < 2; mi++) {
#pragma unroll
        for (int ni = 0; ni < 4; ni++) {
            const int row = row0 + wm + mi * 16 + g;
            const int col = col0 + wn + ni * 8 + tg * 2;
            float2 v0 = {c[mi][ni][0] * scale, c[mi][ni][1] * scale};
            *reinterpret_cast<float2*>(C + (long)row * ldc + col) = v0;
            float2 v1 = {c[mi][ni][2] * scale, c[mi][ni][3] * scale};
            *reinterpret_cast<float2*>(C + (long)(row + 8) * ldc + col) = v1;
        }
    }
}

// ---------------------------------------------------------------------------
// Kernel wrappers
// ---------------------------------------------------------------------------

// Y[M,N] = X[M,K] @ W[K,N]; M=4096, N=K=1024. grid (16, 32)
__global__ void __launch_bounds__(256)
proj_kernel(const float* __restrict__ X,
            const float* __restrict__ W,
            float* __restrict__ Y) {
    gemm_mma<false>(X, Dsz, W, Dsz, Y, Dsz, Dsz, 1.0f);
}

// scores[z,q,k] = (1/8) Q[z,q,:] . K[z,k,:]; grid (32, 16, 32)
__global__ void __launch_bounds__(256)
scores_kernel(float* __restrict__ attn) {
    const int z = blockIdx.z;
    const int b = z / Hsz, h = z % Hsz;
    const float* A  = g_Q + (long)b * Ssz * Dsz + h * DKsz;
    const float* Bm = g_K + (long)b * Ssz * Dsz + h * DKsz;
    float* C = attn + (long)z * Ssz * Ssz;
    gemm_mma<true>(A, Dsz, Bm, Dsz, C, Ssz, DKsz, 0.125f);
}

// Row softmax in place with mask. grid (Ssz, BHsz), block 256
__global__ void __launch_bounds__(256)
softmax_kernel(float* __restrict__ attn, const int* __restrict__ mask) {
    const int row = blockIdx.x;
    const int z   = blockIdx.y;
    const int b   = z / Hsz;
    float* rp = attn + ((long)z * Ssz + row) * Ssz;
    const int* mp = mask + ((long)b * Ssz + row) * Ssz;
    const int t = threadIdx.x;

    float vals[8];
    float mx = -1e30f;
#pragma unroll
    for (int i = 0; i < 8; i++) {
        const int k = t + i * 256;
        float v = rp[k];
        if (mp[k] == 0) v = -1e9f;
        vals[i] = v;
        mx = fmaxf(mx, v);
    }

    __shared__ float red[256];
    red[t] = mx;
    __syncthreads();
#pragma unroll
    for (int s = 128; s > 0; s >>= 1) {
        if (t < s) red[t] = fmaxf(red[t], red[t + s]);
        __syncthreads();
    }
    mx = red[0];
    __syncthreads();

    float sum = 0.0f;
#pragma unroll
    for (int i = 0; i < 8; i++) {
        vals[i] = __expf(vals[i] - mx);
        sum += vals[i];
    }
    red[t] = sum;
    __syncthreads();
#pragma unroll
    for (int s = 128; s > 0; s >>= 1) {
        if (t < s) red[t] += red[t + s];
        __syncthreads();
    }
    const float inv = 1.0f / red[0];

#pragma unroll
    for (int i = 0; i < 8; i++) {
        const int k = t + i * 256;
        rp[k] = vals[i] * inv;
    }
}

// X[z,q,:] = attn[z] @ V[z]; M=2048, N=64, K=2048. grid (1, 16, 32)
__global__ void __launch_bounds__(256)
av_kernel(const float* __restrict__ attn) {
    const int z = blockIdx.z;
    const int b = z / Hsz, h = z % Hsz;
    const float* A  = attn + (long)z * Ssz * Ssz;
    const float* Bm = g_V + (long)b * Ssz * Dsz + h * DKsz;
    float* C = g_X + (long)b * Ssz * Dsz + h * DKsz;
    gemm_mma<false>(A, Ssz, Bm, Dsz, C, Dsz, Ssz, 1.0f);
}

// ---------------------------------------------------------------------------
// Launch
// ---------------------------------------------------------------------------
extern "C" void kernel_launch(void* const* d_in, const int* in_sizes, int n_in,
                              void* d_out, int out_size) {
    const float* query = (const float*)d_in[0];
    const float* key   = (const float*)d_in[1];
    const float* value = (const float*)d_in[2];
    const int*   mask  = (const int*)d_in[3];
    const float* W_q   = (const float*)d_in[4];
    const float* W_k   = (const float*)d_in[5];
    const float* W_v   = (const float*)d_in[6];
    const float* W_o   = (const float*)d_in[7];

    float* out  = (float*)d_out;                        // (B,S,D)
    float* attn = out + (long)Bsz * Ssz * Dsz;          // (B,H,S,S)

    float *Q, *K, *V, *X;
    cudaGetSymbolAddress((void**)&Q, g_Q);
    cudaGetSymbolAddress((void**)&K, g_K);
    cudaGetSymbolAddress((void**)&V, g_V);
    cudaGetSymbolAddress((void**)&X, g_X);

    dim3 projGrid(Dsz / 64, (Bsz * Ssz) / 128);         // (16, 32)
    proj_kernel<<<projGrid, 256>>>(query, W_q, Q);
    proj_kernel<<<projGrid, 256>>>(key,   W_k, K);
    proj_kernel<<<projGrid, 256>>>(value, W_v, V);

    scores_kernel<<<dim3(Ssz / 64, Ssz / 128, BHsz), 256>>>(attn);
    softmax_kernel<<<dim3(Ssz, BHsz), 256>>>(attn, mask);
    av_kernel<<<dim3(1, Ssz / 128, BHsz), 256>>>(attn);

    proj_kernel<<<projGrid, 256>>>(X, W_o, out);
}